// round 8
// baseline (speedup 1.0000x reference)
#include <cuda_runtime.h>
#include <cuda_bf16.h>
#include <math.h>
#include <stdint.h>

#define BATCH 8
#define LQ 2048
#define LK 2048
#define DIM 640
#define INV_TEMP (1.0f / 13.0f)

// ---------------------------------------------------------------------------
// Device scratch (allocation-free rule: __device__ globals)
// split-bf16 concatenated operands: row-major, K' = 2*K (first K = hi, next K = lo)
// ---------------------------------------------------------------------------
__device__ float g_qq[BATCH * LQ];
__device__ float g_kk[BATCH * LK];
__device__ __nv_bfloat16 g_qcat[(size_t)BATCH * LQ * 2 * DIM];   // [B*LQ, 1280]
__device__ __nv_bfloat16 g_kcat[(size_t)BATCH * LK * 2 * DIM];   // [B*LK, 1280]
__device__ __nv_bfloat16 g_vt[(size_t)BATCH * DIM * 2 * LK];     // [B*DIM, 4096] (v^T)
__device__ __nv_bfloat16 g_acat[(size_t)BATCH * LQ * 2 * LK];    // [B*LQ, 4096]

// ---------------------------------------------------------------------------
// helpers
// ---------------------------------------------------------------------------
__device__ __forceinline__ uint32_t smem_u32(const void* p) {
    uint32_t a;
    asm("{ .reg .u64 t; cvta.to.shared.u64 t, %1; cvt.u32.u64 %0, t; }" : "=r"(a) : "l"(p));
    return a;
}
__device__ __forceinline__ void cp16(uint32_t dst, const void* src) {
    asm volatile("cp.async.cg.shared.global [%0], [%1], 16;" :: "r"(dst), "l"(src) : "memory");
}
__device__ __forceinline__ void ldmx4(uint32_t* r, uint32_t addr) {
    asm volatile("ldmatrix.sync.aligned.m8n8.x4.shared.b16 {%0,%1,%2,%3}, [%4];"
                 : "=r"(r[0]), "=r"(r[1]), "=r"(r[2]), "=r"(r[3]) : "r"(addr));
}
__device__ __forceinline__ void mma16816(float* c, const uint32_t* a, uint32_t b0, uint32_t b1) {
    asm volatile(
        "mma.sync.aligned.m16n8k16.row.col.f32.bf16.bf16.f32 "
        "{%0,%1,%2,%3}, {%4,%5,%6,%7}, {%8,%9}, {%0,%1,%2,%3};"
        : "+f"(c[0]), "+f"(c[1]), "+f"(c[2]), "+f"(c[3])
        : "r"(a[0]), "r"(a[1]), "r"(a[2]), "r"(a[3]), "r"(b0), "r"(b1));
}

// ---------------------------------------------------------------------------
// Pass 0a: q,k -> hi/lo bf16 concatenated arrays + row sum-of-squares
// ---------------------------------------------------------------------------
__global__ __launch_bounds__(128)
void conv_qk_kernel(const float* __restrict__ q, const float* __restrict__ k) {
    int row = blockIdx.x;
    bool isQ = row < BATCH * LQ;
    int r = isQ ? row : row - BATCH * LQ;
    const float* src = (isQ ? q : k) + (size_t)r * DIM;
    __nv_bfloat16* dst = (isQ ? g_qcat : g_kcat) + (size_t)r * 2 * DIM;

    float s = 0.f;
    for (int i = threadIdx.x; i < DIM; i += 128) {
        float x = src[i];
        s = fmaf(x, x, s);
        __nv_bfloat16 h = __float2bfloat16(x);
        dst[i] = h;
        dst[DIM + i] = __float2bfloat16(x - __bfloat162float(h));
    }
#pragma unroll
    for (int off = 16; off > 0; off >>= 1)
        s += __shfl_down_sync(0xffffffffu, s, off);
    __shared__ float ws[4];
    if ((threadIdx.x & 31) == 0) ws[threadIdx.x >> 5] = s;
    __syncthreads();
    if (threadIdx.x == 0) {
        float t = ws[0] + ws[1] + ws[2] + ws[3];
        if (isQ) g_qq[r] = t; else g_kk[r] = t;
    }
}

// ---------------------------------------------------------------------------
// Pass 0b: v -> transposed hi/lo bf16: g_vt[(b*DIM+d), k](hi), [.., LK+k](lo)
// ---------------------------------------------------------------------------
__global__ __launch_bounds__(256)
void conv_v_kernel(const float* __restrict__ v) {
    __shared__ float tile[32][33];
    int b = blockIdx.z;
    int k0 = blockIdx.x * 32;
    int d0 = blockIdx.y * 32;
    int tx = threadIdx.x, ty = threadIdx.y;
#pragma unroll
    for (int i = ty; i < 32; i += 8)
        tile[i][tx] = v[((size_t)b * LK + k0 + i) * DIM + d0 + tx];
    __syncthreads();
#pragma unroll
    for (int i = ty; i < 32; i += 8) {
        float x = tile[tx][i];  // v[k0+tx][d0+i]
        __nv_bfloat16 h = __float2bfloat16(x);
        __nv_bfloat16 l = __float2bfloat16(x - __bfloat162float(h));
        size_t rowbase = ((size_t)b * DIM + d0 + i) * (2 * LK);
        g_vt[rowbase + k0 + tx] = h;
        g_vt[rowbase + LK + k0 + tx] = l;
    }
}

// ---------------------------------------------------------------------------
// mma.sync split-bf16 GEMM. CTA tile MT x NT, warps of 64x64 in (MT/64, NT/64).
// A rows: [hi(0:HALFK) | lo(HALFK:2*HALFK)], same for B; 3 passes hh, lh, hl.
// NSTAGE-deep cp.async pipeline, 32-wide k chunks.
// LOGITS: C = (2*acc - qq[m] - kk[n]) / 13.
// ---------------------------------------------------------------------------
template <int MT, int NT, int HALFK, bool LOGITS, int BROWS, int NSTAGE>
__global__ __launch_bounds__((MT / 64) * (NT / 64) * 32, 256 / ((MT / 64) * (NT / 64) * 32))
void gemm_mma_kernel(const __nv_bfloat16* __restrict__ Ag,
                     const __nv_bfloat16* __restrict__ Bg,
                     float* __restrict__ C, int ldc) {
    constexpr int WM = MT / 64;
    constexpr int WN = NT / 64;
    constexpr int NTHR = WM * WN * 32;
    constexpr int STRIDE = 2 * HALFK;
    constexpr int KCH = HALFK / 32;     // 32-wide k chunks per pass
    constexpr int NCH = 3 * KCH;
    constexpr int ABYTES = MT * 64;     // MT rows x 32 bf16
    constexpr int BBYTES = NT * 64;

    extern __shared__ char dsm[];
    const uint32_t uA = smem_u32(dsm);
    const uint32_t uB = uA + NSTAGE * ABYTES;

    int t = threadIdx.x;
    int wid = t >> 5, lane = t & 31;
    int warp_m = wid % WM;
    int warp_n = wid / WM;
    int b = blockIdx.z;
    int m0 = blockIdx.y * MT;
    int n0 = blockIdx.x * NT;
    size_t arow0 = (size_t)b * LQ + m0;
    size_t brow0 = (size_t)b * BROWS + n0;

    auto load_chunk = [&](int ck, int st) {
        int pass = ck / KCH;
        int kc = (ck - pass * KCH) * 32;
        int aoff = (pass == 1) ? HALFK : 0;
        int boff = (pass == 2) ? HALFK : 0;
        const __nv_bfloat16* ab = Ag + arow0 * STRIDE + aoff + kc;
        const __nv_bfloat16* bb = Bg + brow0 * STRIDE + boff + kc;
#pragma unroll
        for (int p = t; p < MT * 4; p += NTHR) {
            int row = p >> 2, c = p & 3;
            int cs = c ^ ((row >> 1) & 3);
            cp16(uA + st * ABYTES + row * 64 + cs * 16, ab + (size_t)row * STRIDE + c * 8);
        }
#pragma unroll
        for (int p = t; p < NT * 4; p += NTHR) {
            int row = p >> 2, c = p & 3;
            int cs = c ^ ((row >> 1) & 3);
            cp16(uB + st * BBYTES + row * 64 + cs * 16, bb + (size_t)row * STRIDE + c * 8);
        }
    };

    float acc[4][8][4];
#pragma unroll
    for (int i = 0; i < 4; i++)
#pragma unroll
        for (int j = 0; j < 8; j++)
#pragma unroll
            for (int u = 0; u < 4; u++) acc[i][j][u] = 0.f;

    // prologue
#pragma unroll
    for (int s = 0; s < NSTAGE - 1; s++) {
        if (s < NCH) load_chunk(s, s);
        asm volatile("cp.async.commit_group;" ::: "memory");
    }

    int lr16 = lane & 15;          // row within 16-row tile
    int hi16 = lane >> 4;          // 16B chunk selector within k16

    for (int s = 0; s < NCH; s++) {
        int pf = s + NSTAGE - 1;
        if (pf < NCH) load_chunk(pf, pf % NSTAGE);
        asm volatile("cp.async.commit_group;" ::: "memory");
        asm volatile("cp.async.wait_group %0;" :: "n"(NSTAGE - 1) : "memory");
        __syncthreads();

        int st = s % NSTAGE;
        uint32_t aBase = uA + st * ABYTES;
        uint32_t bBase = uB + st * BBYTES;
#pragma unroll
        for (int ks = 0; ks < 2; ks++) {
            int c = ks * 2 + hi16;
            uint32_t afr[4][4];
#pragma unroll
            for (int mt = 0; mt < 4; mt++) {
                int row = warp_m * 64 + mt * 16 + lr16;
                int cs = c ^ ((row >> 1) & 3);
                ldmx4(afr[mt], aBase + row * 64 + cs * 16);
            }
            uint32_t bfr[4][4];
#pragma unroll
            for (int np = 0; np < 4; np++) {
                int row = warp_n * 64 + np * 16 + lr16;
                int cs = c ^ ((row >> 1) & 3);
                ldmx4(bfr[np], bBase + row * 64 + cs * 16);
            }
#pragma unroll
            for (int mt = 0; mt < 4; mt++)
#pragma unroll
                for (int nt = 0; nt < 8; nt++) {
                    int np = nt >> 1, sel = nt & 1;
                    mma16816(acc[mt][nt], afr[mt], bfr[np][sel], bfr[np][sel + 2]);
                }
        }
        __syncthreads();
    }

    // ---------------- epilogue ----------------
    int lr = lane >> 2;            // 0..7
    int lc = (lane & 3) * 2;       // 0,2,4,6
#pragma unroll
    for (int mt = 0; mt < 4; mt++) {
#pragma unroll
        for (int h = 0; h < 2; h++) {
            int row = m0 + warp_m * 64 + mt * 16 + h * 8 + lr;
            size_t crow = (size_t)b * LQ + row;
            float qqv = LOGITS ? g_qq[crow] : 0.f;
            float* cp = C + crow * ldc + n0 + warp_n * 64 + lc;
#pragma unroll
            for (int nt = 0; nt < 8; nt++) {
                float v0 = acc[mt][nt][h * 2 + 0];
                float v1 = acc[mt][nt][h * 2 + 1];
                if (LOGITS) {
                    int col = b * LK + n0 + warp_n * 64 + nt * 8 + lc;
                    v0 = (2.f * v0 - qqv - g_kk[col]) * INV_TEMP;
                    v1 = (2.f * v1 - qqv - g_kk[col + 1]) * INV_TEMP;
                }
                float2 w; w.x = v0; w.y = v1;
                *(float2*)(cp + nt * 8) = w;
            }
        }
    }
}

// ---------------------------------------------------------------------------
// Pass 3: row softmax; rewrites log_attn in place, writes attn fp32 and
// attn hi/lo bf16 (g_acat) for the AV GEMM.
// ---------------------------------------------------------------------------
__global__ __launch_bounds__(256)
void softmax_kernel(float* __restrict__ logattn, float* __restrict__ attn) {
    size_t row = blockIdx.x;
    float* lp = logattn + row * LK;
    float* ap = attn + row * LK;
    __nv_bfloat16* acp = g_acat + row * (size_t)(2 * LK);
    int t = threadIdx.x;

    float x[8];
#pragma unroll
    for (int j = 0; j < 8; j++) x[j] = lp[t + j * 256];

    float m = x[0];
#pragma unroll
    for (int j = 1; j < 8; j++) m = fmaxf(m, x[j]);
#pragma unroll
    for (int off = 16; off > 0; off >>= 1)
        m = fmaxf(m, __shfl_xor_sync(0xffffffffu, m, off));
    __shared__ float red[8];
    __shared__ float bval;
    if ((t & 31) == 0) red[t >> 5] = m;
    __syncthreads();
    if (t == 0) {
        float mm = red[0];
#pragma unroll
        for (int w = 1; w < 8; w++) mm = fmaxf(mm, red[w]);
        bval = mm;
    }
    __syncthreads();
    m = bval;

    float s = 0.f;
#pragma unroll
    for (int j = 0; j < 8; j++) s += expf(x[j] - m);
#pragma unroll
    for (int off = 16; off > 0; off >>= 1)
        s += __shfl_xor_sync(0xffffffffu, s, off);
    __syncthreads();
    if ((t & 31) == 0) red[t >> 5] = s;
    __syncthreads();
    if (t == 0) {
        float ss = 0.f;
#pragma unroll
        for (int w = 0; w < 8; w++) ss += red[w];
        bval = m + logf(ss);
    }
    __syncthreads();
    float lse = bval;

#pragma unroll
    for (int j = 0; j < 8; j++) {
        int idx = t + j * 256;
        float la = x[j] - lse;
        float a = expf(la);
        lp[idx] = la;
        ap[idx] = a;
        __nv_bfloat16 h = __float2bfloat16(a);
        acp[idx] = h;
        acp[LK + idx] = __float2bfloat16(a - __bfloat162float(h));
    }
}

// ---------------------------------------------------------------------------
extern "C" void kernel_launch(void* const* d_in, const int* in_sizes, int n_in,
                              void* d_out, int out_size) {
    const float* q = (const float*)d_in[0];
    const float* k = (const float*)d_in[1];
    const float* v = (const float*)d_in[2];

    float* out = (float*)d_out;                            // (B, Lq, D)
    float* attn = out + (size_t)BATCH * LQ * DIM;          // (B, Lq, Lk)
    float* logattn = attn + (size_t)BATCH * LQ * LK;       // (B, Lq, Lk)

    // GEMM1: 128x256 tile, 8 warps, 4 stages: smem = 4*(128+256)*64 = 96KB
    constexpr int SM1 = 4 * (128 * 64 + 256 * 64);
    // GEMM2: 128x128 tile, 4 warps, 4 stages: smem = 4*(128+128)*64 = 64KB
    constexpr int SM2 = 4 * (128 * 64 + 128 * 64);

    auto* k1 = gemm_mma_kernel<128, 256, DIM, true, LK, 4>;
    auto* k2 = gemm_mma_kernel<128, 128, LK, false, DIM, 4>;
    cudaFuncSetAttribute(k1, cudaFuncAttributeMaxDynamicSharedMemorySize, SM1);
    cudaFuncSetAttribute(k2, cudaFuncAttributeMaxDynamicSharedMemorySize, SM2);

    // Pass 0: conversions + row sums of squares
    conv_qk_kernel<<<2 * BATCH * LQ, 128>>>(q, k);
    {
        dim3 g(LK / 32, DIM / 32, BATCH);
        conv_v_kernel<<<g, dim3(32, 8)>>>(v);
    }

    // Pass 1: logits (into log_attn region): A=qcat [B*LQ,1280], B=kcat [B*LK,1280]
    {
        __nv_bfloat16* qc; cudaGetSymbolAddress((void**)&qc, g_qcat);
        __nv_bfloat16* kc; cudaGetSymbolAddress((void**)&kc, g_kcat);
        dim3 g(LK / 256, LQ / 128, BATCH);
        k1<<<g, 256, SM1>>>(qc, kc, logattn, LK);
    }

    // Pass 2: softmax (in-place log_attn, attn fp32, attn bf16 hi/lo)
    softmax_kernel<<<BATCH * LQ, 256>>>(logattn, attn);

    // Pass 3: out = attn @ V: A=acat [B*LQ,4096], B=vt [B*DIM,4096]
    {
        __nv_bfloat16* ac; cudaGetSymbolAddress((void**)&ac, g_acat);
        __nv_bfloat16* vt; cudaGetSymbolAddress((void**)&vt, g_vt);
        dim3 g(DIM / 128, LQ / 128, BATCH);
        k2<<<g, 128, SM2>>>(ac, vt, out, DIM);
    }
}

// round 9
// speedup vs baseline: 1.3901x; 1.3901x over previous
#include <cuda_runtime.h>
#include <cuda_bf16.h>
#include <cuda_fp16.h>
#include <math.h>
#include <stdint.h>

#define BATCH 8
#define LQ 2048
#define LK 2048
#define DIM 640
#define INV_TEMP (1.0f / 13.0f)

// ---------------------------------------------------------------------------
// Device scratch (allocation-free rule: __device__ globals)
// GEMM1 operands: split-bf16 concat rows [hi(0:DIM) | lo(DIM:2*DIM)]
// GEMM2 operands: plain fp16 (attn, v^T)
// ---------------------------------------------------------------------------
__device__ float g_qq[BATCH * LQ];
__device__ float g_kk[BATCH * LK];
__device__ __nv_bfloat16 g_qcat[(size_t)BATCH * LQ * 2 * DIM];   // [B*LQ, 1280]
__device__ __nv_bfloat16 g_kcat[(size_t)BATCH * LK * 2 * DIM];   // [B*LK, 1280]
__device__ __half g_v16[(size_t)BATCH * DIM * LK];               // [B*DIM, 2048] (v^T fp16)
__device__ __half g_a16[(size_t)BATCH * LQ * LK];                // [B*LQ, 2048] (attn fp16)

// ---------------------------------------------------------------------------
// helpers
// ---------------------------------------------------------------------------
__device__ __forceinline__ uint32_t smem_u32(const void* p) {
    uint32_t a;
    asm("{ .reg .u64 t; cvta.to.shared.u64 t, %1; cvt.u32.u64 %0, t; }" : "=r"(a) : "l"(p));
    return a;
}
__device__ __forceinline__ void cp16(uint32_t dst, const void* src) {
    asm volatile("cp.async.cg.shared.global [%0], [%1], 16;" :: "r"(dst), "l"(src) : "memory");
}
__device__ __forceinline__ void ldmx4(uint32_t* r, uint32_t addr) {
    asm volatile("ldmatrix.sync.aligned.m8n8.x4.shared.b16 {%0,%1,%2,%3}, [%4];"
                 : "=r"(r[0]), "=r"(r[1]), "=r"(r[2]), "=r"(r[3]) : "r"(addr));
}
__device__ __forceinline__ void mma_bf16(float* c, const uint32_t* a, uint32_t b0, uint32_t b1) {
    asm volatile(
        "mma.sync.aligned.m16n8k16.row.col.f32.bf16.bf16.f32 "
        "{%0,%1,%2,%3}, {%4,%5,%6,%7}, {%8,%9}, {%0,%1,%2,%3};"
        : "+f"(c[0]), "+f"(c[1]), "+f"(c[2]), "+f"(c[3])
        : "r"(a[0]), "r"(a[1]), "r"(a[2]), "r"(a[3]), "r"(b0), "r"(b1));
}
__device__ __forceinline__ void mma_f16(float* c, const uint32_t* a, uint32_t b0, uint32_t b1) {
    asm volatile(
        "mma.sync.aligned.m16n8k16.row.col.f32.f16.f16.f32 "
        "{%0,%1,%2,%3}, {%4,%5,%6,%7}, {%8,%9}, {%0,%1,%2,%3};"
        : "+f"(c[0]), "+f"(c[1]), "+f"(c[2]), "+f"(c[3])
        : "r"(a[0]), "r"(a[1]), "r"(a[2]), "r"(a[3]), "r"(b0), "r"(b1));
}

// ---------------------------------------------------------------------------
// Pass 0a: q,k -> hi/lo bf16 concatenated arrays + row sum-of-squares
// ---------------------------------------------------------------------------
__global__ __launch_bounds__(128)
void conv_qk_kernel(const float* __restrict__ q, const float* __restrict__ k) {
    int row = blockIdx.x;
    bool isQ = row < BATCH * LQ;
    int r = isQ ? row : row - BATCH * LQ;
    const float* src = (isQ ? q : k) + (size_t)r * DIM;
    __nv_bfloat16* dst = (isQ ? g_qcat : g_kcat) + (size_t)r * 2 * DIM;

    float s = 0.f;
    for (int i = threadIdx.x; i < DIM; i += 128) {
        float x = src[i];
        s = fmaf(x, x, s);
        __nv_bfloat16 h = __float2bfloat16(x);
        dst[i] = h;
        dst[DIM + i] = __float2bfloat16(x - __bfloat162float(h));
    }
#pragma unroll
    for (int off = 16; off > 0; off >>= 1)
        s += __shfl_down_sync(0xffffffffu, s, off);
    __shared__ float ws[4];
    if ((threadIdx.x & 31) == 0) ws[threadIdx.x >> 5] = s;
    __syncthreads();
    if (threadIdx.x == 0) {
        float t = ws[0] + ws[1] + ws[2] + ws[3];
        if (isQ) g_qq[r] = t; else g_kk[r] = t;
    }
}

// ---------------------------------------------------------------------------
// Pass 0b: v -> transposed fp16: g_v16[(b*DIM+d)*LK + k]
// ---------------------------------------------------------------------------
__global__ __launch_bounds__(256)
void conv_v_kernel(const float* __restrict__ v) {
    __shared__ float tile[32][33];
    int b = blockIdx.z;
    int k0 = blockIdx.x * 32;
    int d0 = blockIdx.y * 32;
    int tx = threadIdx.x, ty = threadIdx.y;
#pragma unroll
    for (int i = ty; i < 32; i += 8)
        tile[i][tx] = v[((size_t)b * LK + k0 + i) * DIM + d0 + tx];
    __syncthreads();
#pragma unroll
    for (int i = ty; i < 32; i += 8) {
        float x = tile[tx][i];  // v[k0+tx][d0+i]
        g_v16[((size_t)b * DIM + d0 + i) * LK + k0 + tx] = __float2half(x);
    }
}

// ---------------------------------------------------------------------------
// mma.sync GEMM. CTA tile MT x NT, warps of 64x64 in (MT/64, NT/64).
// NPASS=3 (bf16 split: hh, lh, hl over concat rows of 2*KDIM) or
// NPASS=1 (plain fp16, rows of KDIM).
// NSTAGE-deep cp.async pipeline, 32-wide k chunks.
// LOGITS: C = (2*acc - qq[m] - kk[n]) / 13.
// ---------------------------------------------------------------------------
template <int MT, int NT, int KDIM, int NPASS, bool LOGITS, int BROWS, int NSTAGE, bool F16>
__global__ __launch_bounds__((MT / 64) * (NT / 64) * 32, 256 / ((MT / 64) * (NT / 64) * 32))
void gemm_mma_kernel(const uint16_t* __restrict__ Ag,
                     const uint16_t* __restrict__ Bg,
                     float* __restrict__ C, int ldc) {
    constexpr int WM = MT / 64;
    constexpr int WN = NT / 64;
    constexpr int NTHR = WM * WN * 32;
    constexpr int STRIDE = (NPASS > 1 ? 2 : 1) * KDIM;
    constexpr int KCH = KDIM / 32;      // 32-wide k chunks per pass
    constexpr int NCH = NPASS * KCH;
    constexpr int ABYTES = MT * 64;     // MT rows x 32 elems x 2B
    constexpr int BBYTES = NT * 64;

    extern __shared__ char dsm[];
    const uint32_t uA = smem_u32(dsm);
    const uint32_t uB = uA + NSTAGE * ABYTES;

    int t = threadIdx.x;
    int wid = t >> 5, lane = t & 31;
    int warp_m = wid % WM;
    int warp_n = wid / WM;
    int b = blockIdx.z;
    int m0 = blockIdx.y * MT;
    int n0 = blockIdx.x * NT;
    size_t arow0 = (size_t)b * LQ + m0;
    size_t brow0 = (size_t)b * BROWS + n0;

    auto load_chunk = [&](int ck, int st) {
        int pass = ck / KCH;
        int kc = (ck - pass * KCH) * 32;
        int aoff = (pass == 1) ? KDIM : 0;
        int boff = (pass == 2) ? KDIM : 0;
        const uint16_t* ab = Ag + arow0 * STRIDE + aoff + kc;
        const uint16_t* bb = Bg + brow0 * STRIDE + boff + kc;
#pragma unroll
        for (int p = t; p < MT * 4; p += NTHR) {
            int row = p >> 2, c = p & 3;
            int cs = c ^ ((row >> 1) & 3);
            cp16(uA + st * ABYTES + row * 64 + cs * 16, ab + (size_t)row * STRIDE + c * 8);
        }
#pragma unroll
        for (int p = t; p < NT * 4; p += NTHR) {
            int row = p >> 2, c = p & 3;
            int cs = c ^ ((row >> 1) & 3);
            cp16(uB + st * BBYTES + row * 64 + cs * 16, bb + (size_t)row * STRIDE + c * 8);
        }
    };

    float acc[4][8][4];
#pragma unroll
    for (int i = 0; i < 4; i++)
#pragma unroll
        for (int j = 0; j < 8; j++)
#pragma unroll
            for (int u = 0; u < 4; u++) acc[i][j][u] = 0.f;

    // prologue
#pragma unroll
    for (int s = 0; s < NSTAGE - 1; s++) {
        if (s < NCH) load_chunk(s, s);
        asm volatile("cp.async.commit_group;" ::: "memory");
    }

    int lr16 = lane & 15;          // row within 16-row tile
    int hi16 = lane >> 4;          // 16B chunk selector within k16

    for (int s = 0; s < NCH; s++) {
        int pf = s + NSTAGE - 1;
        if (pf < NCH) load_chunk(pf, pf % NSTAGE);
        asm volatile("cp.async.commit_group;" ::: "memory");
        asm volatile("cp.async.wait_group %0;" :: "n"(NSTAGE - 1) : "memory");
        __syncthreads();

        int st = s % NSTAGE;
        uint32_t aBase = uA + st * ABYTES;
        uint32_t bBase = uB + st * BBYTES;
#pragma unroll
        for (int ks = 0; ks < 2; ks++) {
            int c = ks * 2 + hi16;
            uint32_t afr[4][4];
#pragma unroll
            for (int mt = 0; mt < 4; mt++) {
                int row = warp_m * 64 + mt * 16 + lr16;
                int cs = c ^ ((row >> 1) & 3);
                ldmx4(afr[mt], aBase + row * 64 + cs * 16);
            }
            uint32_t bfr[4][4];
#pragma unroll
            for (int np = 0; np < 4; np++) {
                int row = warp_n * 64 + np * 16 + lr16;
                int cs = c ^ ((row >> 1) & 3);
                ldmx4(bfr[np], bBase + row * 64 + cs * 16);
            }
#pragma unroll
            for (int mt = 0; mt < 4; mt++)
#pragma unroll
                for (int nt = 0; nt < 8; nt++) {
                    int np = nt >> 1, sel = nt & 1;
                    if (F16)
                        mma_f16(acc[mt][nt], afr[mt], bfr[np][sel], bfr[np][sel + 2]);
                    else
                        mma_bf16(acc[mt][nt], afr[mt], bfr[np][sel], bfr[np][sel + 2]);
                }
        }
        __syncthreads();
    }

    // ---------------- epilogue ----------------
    int lr = lane >> 2;            // 0..7
    int lc = (lane & 3) * 2;       // 0,2,4,6
#pragma unroll
    for (int mt = 0; mt < 4; mt++) {
#pragma unroll
        for (int h = 0; h < 2; h++) {
            int row = m0 + warp_m * 64 + mt * 16 + h * 8 + lr;
            size_t crow = (size_t)b * LQ + row;
            float qqv = LOGITS ? g_qq[crow] : 0.f;
            float* cp = C + crow * ldc + n0 + warp_n * 64 + lc;
#pragma unroll
            for (int nt = 0; nt < 8; nt++) {
                float v0 = acc[mt][nt][h * 2 + 0];
                float v1 = acc[mt][nt][h * 2 + 1];
                if (LOGITS) {
                    int col = b * LK + n0 + warp_n * 64 + nt * 8 + lc;
                    v0 = (2.f * v0 - qqv - g_kk[col]) * INV_TEMP;
                    v1 = (2.f * v1 - qqv - g_kk[col + 1]) * INV_TEMP;
                }
                float2 w; w.x = v0; w.y = v1;
                *(float2*)(cp + nt * 8) = w;
            }
        }
    }
}

// ---------------------------------------------------------------------------
// Pass 3: row softmax; rewrites log_attn in place, writes attn fp32 and
// attn fp16 (g_a16) for the AV GEMM.
// ---------------------------------------------------------------------------
__global__ __launch_bounds__(256)
void softmax_kernel(float* __restrict__ logattn, float* __restrict__ attn) {
    size_t row = blockIdx.x;
    float* lp = logattn + row * LK;
    float* ap = attn + row * LK;
    __half* a16 = g_a16 + row * (size_t)LK;
    int t = threadIdx.x;

    float x[8];
#pragma unroll
    for (int j = 0; j < 8; j++) x[j] = lp[t + j * 256];

    float m = x[0];
#pragma unroll
    for (int j = 1; j < 8; j++) m = fmaxf(m, x[j]);
#pragma unroll
    for (int off = 16; off > 0; off >>= 1)
        m = fmaxf(m, __shfl_xor_sync(0xffffffffu, m, off));
    __shared__ float red[8];
    __shared__ float bval;
    if ((t & 31) == 0) red[t >> 5] = m;
    __syncthreads();
    if (t == 0) {
        float mm = red[0];
#pragma unroll
        for (int w = 1; w < 8; w++) mm = fmaxf(mm, red[w]);
        bval = mm;
    }
    __syncthreads();
    m = bval;

    float s = 0.f;
#pragma unroll
    for (int j = 0; j < 8; j++) s += expf(x[j] - m);
#pragma unroll
    for (int off = 16; off > 0; off >>= 1)
        s += __shfl_xor_sync(0xffffffffu, s, off);
    __syncthreads();
    if ((t & 31) == 0) red[t >> 5] = s;
    __syncthreads();
    if (t == 0) {
        float ss = 0.f;
#pragma unroll
        for (int w = 0; w < 8; w++) ss += red[w];
        bval = m + logf(ss);
    }
    __syncthreads();
    float lse = bval;

#pragma unroll
    for (int j = 0; j < 8; j++) {
        int idx = t + j * 256;
        float la = x[j] - lse;
        float a = expf(la);
        lp[idx] = la;
        ap[idx] = a;
        a16[idx] = __float2half(a);
    }
}

// ---------------------------------------------------------------------------
extern "C" void kernel_launch(void* const* d_in, const int* in_sizes, int n_in,
                              void* d_out, int out_size) {
    const float* q = (const float*)d_in[0];
    const float* k = (const float*)d_in[1];
    const float* v = (const float*)d_in[2];

    float* out = (float*)d_out;                            // (B, Lq, D)
    float* attn = out + (size_t)BATCH * LQ * DIM;          // (B, Lq, Lk)
    float* logattn = attn + (size_t)BATCH * LQ * LK;       // (B, Lq, Lk)

    // GEMM1: 128x256, 8 warps, 4 stages, bf16 split 3-pass: smem = 96KB
    constexpr int SM1 = 4 * (128 * 64 + 256 * 64);
    // GEMM2: 128x128, 4 warps, 4 stages, fp16 1-pass: smem = 64KB
    constexpr int SM2 = 4 * (128 * 64 + 128 * 64);

    auto* k1 = gemm_mma_kernel<128, 256, DIM, 3, true, LK, 4, false>;
    auto* k2 = gemm_mma_kernel<128, 128, LK, 1, false, DIM, 4, true>;
    cudaFuncSetAttribute(k1, cudaFuncAttributeMaxDynamicSharedMemorySize, SM1);
    cudaFuncSetAttribute(k2, cudaFuncAttributeMaxDynamicSharedMemorySize, SM2);

    // Pass 0: conversions + row sums of squares
    conv_qk_kernel<<<2 * BATCH * LQ, 128>>>(q, k);
    {
        dim3 g(LK / 32, DIM / 32, BATCH);
        conv_v_kernel<<<g, dim3(32, 8)>>>(v);
    }

    // Pass 1: logits (into log_attn region): A=qcat [B*LQ,1280], B=kcat [B*LK,1280]
    {
        uint16_t* qc; cudaGetSymbolAddress((void**)&qc, g_qcat);
        uint16_t* kc; cudaGetSymbolAddress((void**)&kc, g_kcat);
        dim3 g(LK / 256, LQ / 128, BATCH);
        k1<<<g, 256, SM1>>>(qc, kc, logattn, LK);
    }

    // Pass 2: softmax (in-place log_attn, attn fp32, attn fp16)
    softmax_kernel<<<BATCH * LQ, 256>>>(logattn, attn);

    // Pass 3: out = attn @ V: A=g_a16 [B*LQ,2048], B=g_v16 [B*DIM,2048]
    {
        uint16_t* ac; cudaGetSymbolAddress((void**)&ac, g_a16);
        uint16_t* vt; cudaGetSymbolAddress((void**)&vt, g_v16);
        dim3 g(DIM / 128, LQ / 128, BATCH);
        k2<<<g, 128, SM2>>>(ac, vt, out, DIM);
    }
}

// round 10
// speedup vs baseline: 1.7050x; 1.2265x over previous
#include <cuda_runtime.h>
#include <cuda_bf16.h>
#include <cuda_fp16.h>
#include <math.h>
#include <stdint.h>

#define BATCH 8
#define LQ 2048
#define LK 2048
#define DIM 640
#define INV_TEMP (1.0f / 13.0f)

// ---------------------------------------------------------------------------
// Device scratch (allocation-free rule: __device__ globals)
// GEMM1 operands (fp16 merged split, e = 2^-10):
//   row layout [hi(0:DIM) | mid(DIM:2*DIM)] where
//   hi  = fp16(x)
//   mid = fp16((hi + (x-hi)*2^10) * 2^-5)     (pre-scaled by sqrt(e))
// GEMM2 operands: plain fp16 (attn, v^T)
// ---------------------------------------------------------------------------
__device__ float g_qq[BATCH * LQ];
__device__ float g_kk[BATCH * LK];
__device__ __half g_qcat[(size_t)BATCH * LQ * 2 * DIM];   // [B*LQ, 1280]
__device__ __half g_kcat[(size_t)BATCH * LK * 2 * DIM];   // [B*LK, 1280]
__device__ __half g_v16[(size_t)BATCH * DIM * LK];        // [B*DIM, 2048] (v^T fp16)
__device__ __half g_a16[(size_t)BATCH * LQ * LK];         // [B*LQ, 2048] (attn fp16)

// ---------------------------------------------------------------------------
// helpers
// ---------------------------------------------------------------------------
__device__ __forceinline__ uint32_t smem_u32(const void* p) {
    uint32_t a;
    asm("{ .reg .u64 t; cvta.to.shared.u64 t, %1; cvt.u32.u64 %0, t; }" : "=r"(a) : "l"(p));
    return a;
}
__device__ __forceinline__ void cp16(uint32_t dst, const void* src) {
    asm volatile("cp.async.cg.shared.global [%0], [%1], 16;" :: "r"(dst), "l"(src) : "memory");
}
__device__ __forceinline__ void ldmx4(uint32_t* r, uint32_t addr) {
    asm volatile("ldmatrix.sync.aligned.m8n8.x4.shared.b16 {%0,%1,%2,%3}, [%4];"
                 : "=r"(r[0]), "=r"(r[1]), "=r"(r[2]), "=r"(r[3]) : "r"(addr));
}
__device__ __forceinline__ void mma_f16(float* c, const uint32_t* a, uint32_t b0, uint32_t b1) {
    asm volatile(
        "mma.sync.aligned.m16n8k16.row.col.f32.f16.f16.f32 "
        "{%0,%1,%2,%3}, {%4,%5,%6,%7}, {%8,%9}, {%0,%1,%2,%3};"
        : "+f"(c[0]), "+f"(c[1]), "+f"(c[2]), "+f"(c[3])
        : "r"(a[0]), "r"(a[1]), "r"(a[2]), "r"(a[3]), "r"(b0), "r"(b1));
}

// ---------------------------------------------------------------------------
// Pass 0a: q,k -> fp16 hi/mid concatenated arrays + row sum-of-squares
// ---------------------------------------------------------------------------
__global__ __launch_bounds__(128)
void conv_qk_kernel(const float* __restrict__ q, const float* __restrict__ k) {
    int row = blockIdx.x;
    bool isQ = row < BATCH * LQ;
    int r = isQ ? row : row - BATCH * LQ;
    const float* src = (isQ ? q : k) + (size_t)r * DIM;
    __half* dst = (isQ ? g_qcat : g_kcat) + (size_t)r * 2 * DIM;

    float s = 0.f;
    for (int i = threadIdx.x; i < DIM; i += 128) {
        float x = src[i];
        s = fmaf(x, x, s);
        __half h = __float2half(x);
        float hf = __half2float(h);
        float lt = (x - hf) * 1024.0f;           // q~l, O(1)
        dst[i] = h;
        dst[DIM + i] = __float2half((hf + lt) * 0.03125f);  // * 2^-5 (exact)
    }
#pragma unroll
    for (int off = 16; off > 0; off >>= 1)
        s += __shfl_down_sync(0xffffffffu, s, off);
    __shared__ float ws[4];
    if ((threadIdx.x & 31) == 0) ws[threadIdx.x >> 5] = s;
    __syncthreads();
    if (threadIdx.x == 0) {
        float t = ws[0] + ws[1] + ws[2] + ws[3];
        if (isQ) g_qq[r] = t; else g_kk[r] = t;
    }
}

// ---------------------------------------------------------------------------
// Pass 0b: v -> transposed fp16: g_v16[(b*DIM+d)*LK + k]
// ---------------------------------------------------------------------------
__global__ __launch_bounds__(256)
void conv_v_kernel(const float* __restrict__ v) {
    __shared__ float tile[32][33];
    int b = blockIdx.z;
    int k0 = blockIdx.x * 32;
    int d0 = blockIdx.y * 32;
    int tx = threadIdx.x, ty = threadIdx.y;
#pragma unroll
    for (int i = ty; i < 32; i += 8)
        tile[i][tx] = v[((size_t)b * LK + k0 + i) * DIM + d0 + tx];
    __syncthreads();
#pragma unroll
    for (int i = ty; i < 32; i += 8) {
        float x = tile[tx][i];  // v[k0+tx][d0+i]
        g_v16[((size_t)b * DIM + d0 + i) * LK + k0 + tx] = __float2half(x);
    }
}

// ---------------------------------------------------------------------------
// mma.sync fp16 GEMM. CTA tile MT x NT, warps of 64x64 in (MT/64, NT/64).
// NPASS=2 (merged split: pass0 = hi*hi, then acc *= (1-2^-10), pass1 adds
//          e*mid*mid via pre-scaled operands; rows of 2*KDIM)
// NPASS=1 (plain fp16, rows of KDIM).
// NSTAGE-deep cp.async pipeline, 32-wide k chunks.
// LOGITS: C = (2*acc - qq[m] - kk[n]) / 13.
// ---------------------------------------------------------------------------
template <int MT, int NT, int KDIM, int NPASS, bool LOGITS, int BROWS, int NSTAGE>
__global__ __launch_bounds__((MT / 64) * (NT / 64) * 32, 256 / ((MT / 64) * (NT / 64) * 32))
void gemm_mma_kernel(const uint16_t* __restrict__ Ag,
                     const uint16_t* __restrict__ Bg,
                     float* __restrict__ C, int ldc) {
    constexpr int WM = MT / 64;
    constexpr int WN = NT / 64;
    constexpr int NTHR = WM * WN * 32;
    constexpr int STRIDE = NPASS * KDIM;
    constexpr int KCH = KDIM / 32;      // 32-wide k chunks per pass
    constexpr int NCH = NPASS * KCH;
    constexpr int ABYTES = MT * 64;     // MT rows x 32 elems x 2B
    constexpr int BBYTES = NT * 64;

    extern __shared__ char dsm[];
    const uint32_t uA = smem_u32(dsm);
    const uint32_t uB = uA + NSTAGE * ABYTES;

    int t = threadIdx.x;
    int wid = t >> 5, lane = t & 31;
    int warp_m = wid % WM;
    int warp_n = wid / WM;
    int b = blockIdx.z;
    int m0 = blockIdx.y * MT;
    int n0 = blockIdx.x * NT;
    size_t arow0 = (size_t)b * LQ + m0;
    size_t brow0 = (size_t)b * BROWS + n0;

    auto load_chunk = [&](int ck, int st) {
        int pass = ck / KCH;
        int kc = (ck - pass * KCH) * 32;
        int off = (pass == 1) ? KDIM : 0;
        const uint16_t* ab = Ag + arow0 * STRIDE + off + kc;
        const uint16_t* bb = Bg + brow0 * STRIDE + off + kc;
#pragma unroll
        for (int p = t; p < MT * 4; p += NTHR) {
            int row = p >> 2, c = p & 3;
            int cs = c ^ ((row >> 1) & 3);
            cp16(uA + st * ABYTES + row * 64 + cs * 16, ab + (size_t)row * STRIDE + c * 8);
        }
#pragma unroll
        for (int p = t; p < NT * 4; p += NTHR) {
            int row = p >> 2, c = p & 3;
            int cs = c ^ ((row >> 1) & 3);
            cp16(uB + st * BBYTES + row * 64 + cs * 16, bb + (size_t)row * STRIDE + c * 8);
        }
    };

    float acc[4][8][4];
#pragma unroll
    for (int i = 0; i < 4; i++)
#pragma unroll
        for (int j = 0; j < 8; j++)
#pragma unroll
            for (int u = 0; u < 4; u++) acc[i][j][u] = 0.f;

    // prologue
#pragma unroll
    for (int s = 0; s < NSTAGE - 1; s++) {
        if (s < NCH) load_chunk(s, s);
        asm volatile("cp.async.commit_group;" ::: "memory");
    }

    int lr16 = lane & 15;          // row within 16-row tile
    int hi16 = lane >> 4;          // 16B chunk selector within k16

    for (int s = 0; s < NCH; s++) {
        int pf = s + NSTAGE - 1;
        if (pf < NCH) load_chunk(pf, pf % NSTAGE);
        asm volatile("cp.async.commit_group;" ::: "memory");
        asm volatile("cp.async.wait_group %0;" :: "n"(NSTAGE - 1) : "memory");
        __syncthreads();

        // pass boundary: acc = (1 - e) * pass0 before pass1 MMAs begin
        if (NPASS == 2 && s == KCH) {
#pragma unroll
            for (int i = 0; i < 4; i++)
#pragma unroll
                for (int j = 0; j < 8; j++)
#pragma unroll
                    for (int u = 0; u < 4; u++)
                        acc[i][j][u] *= 0.9990234375f;   // 1 - 2^-10 (exact fp32)
        }

        int st = s % NSTAGE;
        uint32_t aBase = uA + st * ABYTES;
        uint32_t bBase = uB + st * BBYTES;
#pragma unroll
        for (int ks = 0; ks < 2; ks++) {
            int c = ks * 2 + hi16;
            uint32_t afr[4][4];
#pragma unroll
            for (int mt = 0; mt < 4; mt++) {
                int row = warp_m * 64 + mt * 16 + lr16;
                int cs = c ^ ((row >> 1) & 3);
                ldmx4(afr[mt], aBase + row * 64 + cs * 16);
            }
            uint32_t bfr[4][4];
#pragma unroll
            for (int np = 0; np < 4; np++) {
                int row = warp_n * 64 + np * 16 + lr16;
                int cs = c ^ ((row >> 1) & 3);
                ldmx4(bfr[np], bBase + row * 64 + cs * 16);
            }
#pragma unroll
            for (int mt = 0; mt < 4; mt++)
#pragma unroll
                for (int nt = 0; nt < 8; nt++) {
                    int np = nt >> 1, sel = nt & 1;
                    mma_f16(acc[mt][nt], afr[mt], bfr[np][sel], bfr[np][sel + 2]);
                }
        }
        __syncthreads();
    }

    // ---------------- epilogue ----------------
    int lr = lane >> 2;            // 0..7
    int lc = (lane & 3) * 2;       // 0,2,4,6
#pragma unroll
    for (int mt = 0; mt < 4; mt++) {
#pragma unroll
        for (int h = 0; h < 2; h++) {
            int row = m0 + warp_m * 64 + mt * 16 + h * 8 + lr;
            size_t crow = (size_t)b * LQ + row;
            float qqv = LOGITS ? g_qq[crow] : 0.f;
            float* cp = C + crow * ldc + n0 + warp_n * 64 + lc;
#pragma unroll
            for (int nt = 0; nt < 8; nt++) {
                float v0 = acc[mt][nt][h * 2 + 0];
                float v1 = acc[mt][nt][h * 2 + 1];
                if (LOGITS) {
                    int col = b * LK + n0 + warp_n * 64 + nt * 8 + lc;
                    v0 = (2.f * v0 - qqv - g_kk[col]) * INV_TEMP;
                    v1 = (2.f * v1 - qqv - g_kk[col + 1]) * INV_TEMP;
                }
                float2 w; w.x = v0; w.y = v1;
                *(float2*)(cp + nt * 8) = w;
            }
        }
    }
}

// ---------------------------------------------------------------------------
// Pass 3: row softmax; rewrites log_attn in place, writes attn fp32 and
// attn fp16 (g_a16) for the AV GEMM.
// ---------------------------------------------------------------------------
__global__ __launch_bounds__(256)
void softmax_kernel(float* __restrict__ logattn, float* __restrict__ attn) {
    size_t row = blockIdx.x;
    float* lp = logattn + row * LK;
    float* ap = attn + row * LK;
    __half* a16 = g_a16 + row * (size_t)LK;
    int t = threadIdx.x;

    float x[8];
#pragma unroll
    for (int j = 0; j < 8; j++) x[j] = lp[t + j * 256];

    float m = x[0];
#pragma unroll
    for (int j = 1; j < 8; j++) m = fmaxf(m, x[j]);
#pragma unroll
    for (int off = 16; off > 0; off >>= 1)
        m = fmaxf(m, __shfl_xor_sync(0xffffffffu, m, off));
    __shared__ float red[8];
    __shared__ float bval;
    if ((t & 31) == 0) red[t >> 5] = m;
    __syncthreads();
    if (t == 0) {
        float mm = red[0];
#pragma unroll
        for (int w = 1; w < 8; w++) mm = fmaxf(mm, red[w]);
        bval = mm;
    }
    __syncthreads();
    m = bval;

    float s = 0.f;
#pragma unroll
    for (int j = 0; j < 8; j++) s += expf(x[j] - m);
#pragma unroll
    for (int off = 16; off > 0; off >>= 1)
        s += __shfl_xor_sync(0xffffffffu, s, off);
    __syncthreads();
    if ((t & 31) == 0) red[t >> 5] = s;
    __syncthreads();
    if (t == 0) {
        float ss = 0.f;
#pragma unroll
        for (int w = 0; w < 8; w++) ss += red[w];
        bval = m + logf(ss);
    }
    __syncthreads();
    float lse = bval;

#pragma unroll
    for (int j = 0; j < 8; j++) {
        int idx = t + j * 256;
        float la = x[j] - lse;
        float a = expf(la);
        lp[idx] = la;
        ap[idx] = a;
        a16[idx] = __float2half(a);
    }
}

// ---------------------------------------------------------------------------
extern "C" void kernel_launch(void* const* d_in, const int* in_sizes, int n_in,
                              void* d_out, int out_size) {
    const float* q = (const float*)d_in[0];
    const float* k = (const float*)d_in[1];
    const float* v = (const float*)d_in[2];

    float* out = (float*)d_out;                            // (B, Lq, D)
    float* attn = out + (size_t)BATCH * LQ * DIM;          // (B, Lq, Lk)
    float* logattn = attn + (size_t)BATCH * LQ * LK;       // (B, Lq, Lk)

    // GEMM1: 128x256, 8 warps, 4 stages, fp16 merged 2-pass: smem = 96KB
    constexpr int SM1 = 4 * (128 * 64 + 256 * 64);
    // GEMM2: 128x128, 4 warps, 4 stages, fp16 1-pass: smem = 64KB
    constexpr int SM2 = 4 * (128 * 64 + 128 * 64);

    auto* k1 = gemm_mma_kernel<128, 256, DIM, 2, true, LK, 4>;
    auto* k2 = gemm_mma_kernel<128, 128, LK, 1, false, DIM, 4>;
    cudaFuncSetAttribute(k1, cudaFuncAttributeMaxDynamicSharedMemorySize, SM1);
    cudaFuncSetAttribute(k2, cudaFuncAttributeMaxDynamicSharedMemorySize, SM2);

    // Pass 0: conversions + row sums of squares
    conv_qk_kernel<<<2 * BATCH * LQ, 128>>>(q, k);
    {
        dim3 g(LK / 32, DIM / 32, BATCH);
        conv_v_kernel<<<g, dim3(32, 8)>>>(v);
    }

    // Pass 1: logits (into log_attn region): A=qcat [B*LQ,1280], B=kcat [B*LK,1280]
    {
        uint16_t* qc; cudaGetSymbolAddress((void**)&qc, g_qcat);
        uint16_t* kc; cudaGetSymbolAddress((void**)&kc, g_kcat);
        dim3 g(LK / 256, LQ / 128, BATCH);
        k1<<<g, 256, SM1>>>(qc, kc, logattn, LK);
    }

    // Pass 2: softmax (in-place log_attn, attn fp32, attn fp16)
    softmax_kernel<<<BATCH * LQ, 256>>>(logattn, attn);

    // Pass 3: out = attn @ V: A=g_a16 [B*LQ,2048], B=g_v16 [B*DIM,2048]
    {
        uint16_t* ac; cudaGetSymbolAddress((void**)&ac, g_a16);
        uint16_t* vt; cudaGetSymbolAddress((void**)&vt, g_v16);
        dim3 g(DIM / 128, LQ / 128, BATCH);
        k2<<<g, 128, SM2>>>(ac, vt, out, DIM);
    }
}

// round 11
// speedup vs baseline: 1.7647x; 1.0350x over previous
#include <cuda_runtime.h>
#include <cuda_bf16.h>
#include <cuda_fp16.h>
#include <math.h>
#include <stdint.h>

#define BATCH 8
#define LQ 2048
#define LK 2048
#define DIM 640
#define INV_TEMP (1.0f / 13.0f)

// ---------------------------------------------------------------------------
// Device scratch (allocation-free rule: __device__ globals)
// GEMM1 operands (fp16 merged split, e = 2^-10):
//   row layout [hi(0:DIM) | mid(DIM:2*DIM)] where
//   hi  = fp16(x)
//   mid = fp16((hi + (x-hi)*2^10) * 2^-5)     (pre-scaled by sqrt(e))
// GEMM2 operands: plain fp16 (attn, v^T)
// ---------------------------------------------------------------------------
__device__ float g_qq[BATCH * LQ];
__device__ float g_kk[BATCH * LK];
__device__ __half g_qcat[(size_t)BATCH * LQ * 2 * DIM];   // [B*LQ, 1280]
__device__ __half g_kcat[(size_t)BATCH * LK * 2 * DIM];   // [B*LK, 1280]
__device__ __half g_v16[(size_t)BATCH * DIM * LK];        // [B*DIM, 2048] (v^T fp16)
__device__ __half g_a16[(size_t)BATCH * LQ * LK];         // [B*LQ, 2048] (attn fp16)

// ---------------------------------------------------------------------------
// helpers
// ---------------------------------------------------------------------------
__device__ __forceinline__ uint32_t smem_u32(const void* p) {
    uint32_t a;
    asm("{ .reg .u64 t; cvta.to.shared.u64 t, %1; cvt.u32.u64 %0, t; }" : "=r"(a) : "l"(p));
    return a;
}
__device__ __forceinline__ void cp16(uint32_t dst, const void* src) {
    asm volatile("cp.async.cg.shared.global [%0], [%1], 16;" :: "r"(dst), "l"(src) : "memory");
}
__device__ __forceinline__ void ldmx4(uint32_t* r, uint32_t addr) {
    asm volatile("ldmatrix.sync.aligned.m8n8.x4.shared.b16 {%0,%1,%2,%3}, [%4];"
                 : "=r"(r[0]), "=r"(r[1]), "=r"(r[2]), "=r"(r[3]) : "r"(addr));
}
__device__ __forceinline__ void mma_f16(float* c, const uint32_t* a, uint32_t b0, uint32_t b1) {
    asm volatile(
        "mma.sync.aligned.m16n8k16.row.col.f32.f16.f16.f32 "
        "{%0,%1,%2,%3}, {%4,%5,%6,%7}, {%8,%9}, {%0,%1,%2,%3};"
        : "+f"(c[0]), "+f"(c[1]), "+f"(c[2]), "+f"(c[3])
        : "r"(a[0]), "r"(a[1]), "r"(a[2]), "r"(a[3]), "r"(b0), "r"(b1));
}

// ---------------------------------------------------------------------------
// Pass 0a: q,k -> fp16 hi/mid concatenated arrays + row sum-of-squares
// 160 threads per row, float4 loads (640 = 160*4).
// ---------------------------------------------------------------------------
__global__ __launch_bounds__(160)
void conv_qk_kernel(const float* __restrict__ q, const float* __restrict__ k) {
    int row = blockIdx.x;
    bool isQ = row < BATCH * LQ;
    int r = isQ ? row : row - BATCH * LQ;
    const float4* src = (const float4*)((isQ ? q : k) + (size_t)r * DIM);
    __half* dst = (isQ ? g_qcat : g_kcat) + (size_t)r * 2 * DIM;

    int t = threadIdx.x;
    float4 x4 = src[t];
    float xs[4] = {x4.x, x4.y, x4.z, x4.w};
    float s = 0.f;
    __half2 hi2[2], mid2[2];
#pragma unroll
    for (int u = 0; u < 2; u++) {
        float a = xs[u * 2], bb = xs[u * 2 + 1];
        s = fmaf(a, a, s);
        s = fmaf(bb, bb, s);
        __half ha = __float2half(a), hb = __float2half(bb);
        float fa = __half2float(ha), fb = __half2float(hb);
        float ma = (fa + (a - fa) * 1024.0f) * 0.03125f;
        float mb = (fb + (bb - fb) * 1024.0f) * 0.03125f;
        hi2[u] = __halves2half2(ha, hb);
        mid2[u] = __halves2half2(__float2half(ma), __float2half(mb));
    }
    *(__half2*)(dst + t * 4) = hi2[0];
    *(__half2*)(dst + t * 4 + 2) = hi2[1];
    *(__half2*)(dst + DIM + t * 4) = mid2[0];
    *(__half2*)(dst + DIM + t * 4 + 2) = mid2[1];

#pragma unroll
    for (int off = 16; off > 0; off >>= 1)
        s += __shfl_down_sync(0xffffffffu, s, off);
    __shared__ float ws[5];
    if ((t & 31) == 0) ws[t >> 5] = s;
    __syncthreads();
    if (t == 0) {
        float tt = ws[0] + ws[1] + ws[2] + ws[3] + ws[4];
        if (isQ) g_qq[r] = tt; else g_kk[r] = tt;
    }
}

// ---------------------------------------------------------------------------
// Pass 0b: v -> transposed fp16: g_v16[(b*DIM+d)*LK + k]
// ---------------------------------------------------------------------------
__global__ __launch_bounds__(256)
void conv_v_kernel(const float* __restrict__ v) {
    __shared__ float tile[32][33];
    int b = blockIdx.z;
    int k0 = blockIdx.x * 32;
    int d0 = blockIdx.y * 32;
    int tx = threadIdx.x, ty = threadIdx.y;
#pragma unroll
    for (int i = ty; i < 32; i += 8)
        tile[i][tx] = v[((size_t)b * LK + k0 + i) * DIM + d0 + tx];
    __syncthreads();
#pragma unroll
    for (int i = ty; i < 32; i += 8) {
        float x = tile[tx][i];  // v[k0+tx][d0+i]
        g_v16[((size_t)b * DIM + d0 + i) * LK + k0 + tx] = __float2half(x);
    }
}

// ---------------------------------------------------------------------------
// mma.sync fp16 GEMM. CTA tile MT x NT, warps of 64x64 in (MT/64, NT/64).
// NPASS=2 (merged split: pass0 = hi*hi, then acc *= (1-2^-10), pass1 adds
//          e*mid*mid via pre-scaled operands; rows of 2*KDIM)
// NPASS=1 (plain fp16, rows of KDIM).
// NSTAGE-deep cp.async pipeline, 32-wide k chunks.
// LOGITS: C = (2*acc - qq[m] - kk[n]) / 13.
// ---------------------------------------------------------------------------
template <int MT, int NT, int KDIM, int NPASS, bool LOGITS, int BROWS, int NSTAGE>
__global__ __launch_bounds__((MT / 64) * (NT / 64) * 32, 256 / ((MT / 64) * (NT / 64) * 32))
void gemm_mma_kernel(const uint16_t* __restrict__ Ag,
                     const uint16_t* __restrict__ Bg,
                     float* __restrict__ C, int ldc) {
    constexpr int WM = MT / 64;
    constexpr int WN = NT / 64;
    constexpr int NTHR = WM * WN * 32;
    constexpr int STRIDE = NPASS * KDIM;
    constexpr int KCH = KDIM / 32;      // 32-wide k chunks per pass
    constexpr int NCH = NPASS * KCH;
    constexpr int ABYTES = MT * 64;     // MT rows x 32 elems x 2B
    constexpr int BBYTES = NT * 64;

    extern __shared__ char dsm[];
    const uint32_t uA = smem_u32(dsm);
    const uint32_t uB = uA + NSTAGE * ABYTES;

    int t = threadIdx.x;
    int wid = t >> 5, lane = t & 31;
    int warp_m = wid % WM;
    int warp_n = wid / WM;
    int b = blockIdx.z;
    int m0 = blockIdx.y * MT;
    int n0 = blockIdx.x * NT;
    size_t arow0 = (size_t)b * LQ + m0;
    size_t brow0 = (size_t)b * BROWS + n0;

    auto load_chunk = [&](int ck, int st) {
        int pass = ck / KCH;
        int kc = (ck - pass * KCH) * 32;
        int off = (pass == 1) ? KDIM : 0;
        const uint16_t* ab = Ag + arow0 * STRIDE + off + kc;
        const uint16_t* bb = Bg + brow0 * STRIDE + off + kc;
#pragma unroll
        for (int p = t; p < MT * 4; p += NTHR) {
            int row = p >> 2, c = p & 3;
            int cs = c ^ ((row >> 1) & 3);
            cp16(uA + st * ABYTES + row * 64 + cs * 16, ab + (size_t)row * STRIDE + c * 8);
        }
#pragma unroll
        for (int p = t; p < NT * 4; p += NTHR) {
            int row = p >> 2, c = p & 3;
            int cs = c ^ ((row >> 1) & 3);
            cp16(uB + st * BBYTES + row * 64 + cs * 16, bb + (size_t)row * STRIDE + c * 8);
        }
    };

    float acc[4][8][4];
#pragma unroll
    for (int i = 0; i < 4; i++)
#pragma unroll
        for (int j = 0; j < 8; j++)
#pragma unroll
            for (int u = 0; u < 4; u++) acc[i][j][u] = 0.f;

    // prologue
#pragma unroll
    for (int s = 0; s < NSTAGE - 1; s++) {
        if (s < NCH) load_chunk(s, s);
        asm volatile("cp.async.commit_group;" ::: "memory");
    }

    int lr16 = lane & 15;          // row within 16-row tile
    int hi16 = lane >> 4;          // 16B chunk selector within k16

    for (int s = 0; s < NCH; s++) {
        int pf = s + NSTAGE - 1;
        if (pf < NCH) load_chunk(pf, pf % NSTAGE);
        asm volatile("cp.async.commit_group;" ::: "memory");
        asm volatile("cp.async.wait_group %0;" :: "n"(NSTAGE - 1) : "memory");
        __syncthreads();

        // pass boundary: acc = (1 - e) * pass0 before pass1 MMAs begin
        if (NPASS == 2 && s == KCH) {
#pragma unroll
            for (int i = 0; i < 4; i++)
#pragma unroll
                for (int j = 0; j < 8; j++)
#pragma unroll
                    for (int u = 0; u < 4; u++)
                        acc[i][j][u] *= 0.9990234375f;   // 1 - 2^-10 (exact fp32)
        }

        int st = s % NSTAGE;
        uint32_t aBase = uA + st * ABYTES;
        uint32_t bBase = uB + st * BBYTES;
#pragma unroll
        for (int ks = 0; ks < 2; ks++) {
            int c = ks * 2 + hi16;
            uint32_t afr[4][4];
#pragma unroll
            for (int mt = 0; mt < 4; mt++) {
                int row = warp_m * 64 + mt * 16 + lr16;
                int cs = c ^ ((row >> 1) & 3);
                ldmx4(afr[mt], aBase + row * 64 + cs * 16);
            }
            uint32_t bfr[4][4];
#pragma unroll
            for (int np = 0; np < 4; np++) {
                int row = warp_n * 64 + np * 16 + lr16;
                int cs = c ^ ((row >> 1) & 3);
                ldmx4(bfr[np], bBase + row * 64 + cs * 16);
            }
#pragma unroll
            for (int mt = 0; mt < 4; mt++)
#pragma unroll
                for (int nt = 0; nt < 8; nt++) {
                    int np = nt >> 1, sel = nt & 1;
                    mma_f16(acc[mt][nt], afr[mt], bfr[np][sel], bfr[np][sel + 2]);
                }
        }
        __syncthreads();
    }

    // ---------------- epilogue ----------------
    int lr = lane >> 2;            // 0..7
    int lc = (lane & 3) * 2;       // 0,2,4,6
#pragma unroll
    for (int mt = 0; mt < 4; mt++) {
#pragma unroll
        for (int h = 0; h < 2; h++) {
            int row = m0 + warp_m * 64 + mt * 16 + h * 8 + lr;
            size_t crow = (size_t)b * LQ + row;
            float qqv = LOGITS ? g_qq[crow] : 0.f;
            float* cp = C + crow * ldc + n0 + warp_n * 64 + lc;
#pragma unroll
            for (int nt = 0; nt < 8; nt++) {
                float v0 = acc[mt][nt][h * 2 + 0];
                float v1 = acc[mt][nt][h * 2 + 1];
                if (LOGITS) {
                    int col = b * LK + n0 + warp_n * 64 + nt * 8 + lc;
                    v0 = (2.f * v0 - qqv - g_kk[col]) * INV_TEMP;
                    v1 = (2.f * v1 - qqv - g_kk[col + 1]) * INV_TEMP;
                }
                float2 w; w.x = v0; w.y = v1;
                *(float2*)(cp + nt * 8) = w;
            }
        }
    }
}

// ---------------------------------------------------------------------------
// Pass 3: row softmax; rewrites log_attn in place, writes attn fp32 and
// attn fp16 (g_a16) for the AV GEMM. float4-vectorized.
// Thread t handles 8 contiguous elems at t*8.
// ---------------------------------------------------------------------------
__global__ __launch_bounds__(256)
void softmax_kernel(float* __restrict__ logattn, float* __restrict__ attn) {
    size_t row = blockIdx.x;
    float4* lp4 = (float4*)(logattn + row * LK);
    float4* ap4 = (float4*)(attn + row * LK);
    __half2* a16 = (__half2*)(g_a16 + row * (size_t)LK);
    int t = threadIdx.x;

    float4 xa = lp4[t * 2];
    float4 xb = lp4[t * 2 + 1];
    float x[8] = {xa.x, xa.y, xa.z, xa.w, xb.x, xb.y, xb.z, xb.w};

    float m = x[0];
#pragma unroll
    for (int j = 1; j < 8; j++) m = fmaxf(m, x[j]);
#pragma unroll
    for (int off = 16; off > 0; off >>= 1)
        m = fmaxf(m, __shfl_xor_sync(0xffffffffu, m, off));
    __shared__ float red[8];
    __shared__ float bval;
    if ((t & 31) == 0) red[t >> 5] = m;
    __syncthreads();
    if (t == 0) {
        float mm = red[0];
#pragma unroll
        for (int w = 1; w < 8; w++) mm = fmaxf(mm, red[w]);
        bval = mm;
    }
    __syncthreads();
    m = bval;

    float s = 0.f;
#pragma unroll
    for (int j = 0; j < 8; j++) s += expf(x[j] - m);
#pragma unroll
    for (int off = 16; off > 0; off >>= 1)
        s += __shfl_xor_sync(0xffffffffu, s, off);
    __syncthreads();
    if ((t & 31) == 0) red[t >> 5] = s;
    __syncthreads();
    if (t == 0) {
        float ss = 0.f;
#pragma unroll
        for (int w = 0; w < 8; w++) ss += red[w];
        bval = m + logf(ss);
    }
    __syncthreads();
    float lse = bval;

    float la[8], a[8];
#pragma unroll
    for (int j = 0; j < 8; j++) {
        la[j] = x[j] - lse;
        a[j] = expf(la[j]);
    }
    float4 w0 = {la[0], la[1], la[2], la[3]};
    float4 w1 = {la[4], la[5], la[6], la[7]};
    lp4[t * 2] = w0;
    lp4[t * 2 + 1] = w1;
    float4 v0 = {a[0], a[1], a[2], a[3]};
    float4 v1 = {a[4], a[5], a[6], a[7]};
    ap4[t * 2] = v0;
    ap4[t * 2 + 1] = v1;
#pragma unroll
    for (int u = 0; u < 4; u++)
        a16[t * 4 + u] = __floats2half2_rn(a[u * 2], a[u * 2 + 1]);
}

// ---------------------------------------------------------------------------
extern "C" void kernel_launch(void* const* d_in, const int* in_sizes, int n_in,
                              void* d_out, int out_size) {
    const float* q = (const float*)d_in[0];
    const float* k = (const float*)d_in[1];
    const float* v = (const float*)d_in[2];

    float* out = (float*)d_out;                            // (B, Lq, D)
    float* attn = out + (size_t)BATCH * LQ * DIM;          // (B, Lq, Lk)
    float* logattn = attn + (size_t)BATCH * LQ * LK;       // (B, Lq, Lk)

    // GEMM1: 128x256, 8 warps, 4 stages, fp16 merged 2-pass: smem = 96KB
    constexpr int SM1 = 4 * (128 * 64 + 256 * 64);
    // GEMM2: 64x128, 2 warps, 4 stages, fp16 1-pass: smem = 48KB
    constexpr int SM2 = 4 * (64 * 64 + 128 * 64);

    auto* k1 = gemm_mma_kernel<128, 256, DIM, 2, true, LK, 4>;
    auto* k2 = gemm_mma_kernel<64, 128, LK, 1, false, DIM, 4>;
    cudaFuncSetAttribute(k1, cudaFuncAttributeMaxDynamicSharedMemorySize, SM1);
    cudaFuncSetAttribute(k2, cudaFuncAttributeMaxDynamicSharedMemorySize, SM2);

    // Pass 0: conversions + row sums of squares
    conv_qk_kernel<<<2 * BATCH * LQ, 160>>>(q, k);
    {
        dim3 g(LK / 32, DIM / 32, BATCH);
        conv_v_kernel<<<g, dim3(32, 8)>>>(v);
    }

    // Pass 1: logits (into log_attn region): A=qcat [B*LQ,1280], B=kcat [B*LK,1280]
    {
        uint16_t* qc; cudaGetSymbolAddress((void**)&qc, g_qcat);
        uint16_t* kc; cudaGetSymbolAddress((void**)&kc, g_kcat);
        dim3 g(LK / 256, LQ / 128, BATCH);
        k1<<<g, 256, SM1>>>(qc, kc, logattn, LK);
    }

    // Pass 2: softmax (in-place log_attn, attn fp32, attn fp16)
    softmax_kernel<<<BATCH * LQ, 256>>>(logattn, attn);

    // Pass 3: out = attn @ V: A=g_a16 [B*LQ,2048], B=g_v16 [B*DIM,2048]
    {
        uint16_t* ac; cudaGetSymbolAddress((void**)&ac, g_a16);
        uint16_t* vt; cudaGetSymbolAddress((void**)&vt, g_v16);
        dim3 g(DIM / 128, LQ / 64, BATCH);
        k2<<<g, 64, SM2>>>(ac, vt, out, DIM);
    }
}

// round 12
// speedup vs baseline: 1.7749x; 1.0058x over previous
#include <cuda_runtime.h>
#include <cuda_bf16.h>
#include <cuda_fp16.h>
#include <math.h>
#include <stdint.h>

#define BATCH 8
#define LQ 2048
#define LK 2048
#define DIM 640
#define INV_TEMP (1.0f / 13.0f)

// ---------------------------------------------------------------------------
// Device scratch (allocation-free rule: __device__ globals)
// GEMM1 operands (fp16 merged split, e = 2^-10):
//   row layout [hi(0:DIM) | mid(DIM:2*DIM)] where
//   hi  = fp16(x)
//   mid = fp16((hi + (x-hi)*2^10) * 2^-5)     (pre-scaled by sqrt(e))
// GEMM2 operands: plain fp16 (attn, v^T)
// ---------------------------------------------------------------------------
__device__ float g_qq[BATCH * LQ];
__device__ float g_kk[BATCH * LK];
__device__ __half g_qcat[(size_t)BATCH * LQ * 2 * DIM];   // [B*LQ, 1280]
__device__ __half g_kcat[(size_t)BATCH * LK * 2 * DIM];   // [B*LK, 1280]
__device__ __half g_v16[(size_t)BATCH * DIM * LK];        // [B*DIM, 2048] (v^T fp16)
__device__ __half g_a16[(size_t)BATCH * LQ * LK];         // [B*LQ, 2048] (attn fp16)

// ---------------------------------------------------------------------------
// helpers
// ---------------------------------------------------------------------------
__device__ __forceinline__ uint32_t smem_u32(const void* p) {
    uint32_t a;
    asm("{ .reg .u64 t; cvta.to.shared.u64 t, %1; cvt.u32.u64 %0, t; }" : "=r"(a) : "l"(p));
    return a;
}
__device__ __forceinline__ void cp16(uint32_t dst, const void* src) {
    asm volatile("cp.async.cg.shared.global [%0], [%1], 16;" :: "r"(dst), "l"(src) : "memory");
}
__device__ __forceinline__ void ldmx4(uint32_t* r, uint32_t addr) {
    asm volatile("ldmatrix.sync.aligned.m8n8.x4.shared.b16 {%0,%1,%2,%3}, [%4];"
                 : "=r"(r[0]), "=r"(r[1]), "=r"(r[2]), "=r"(r[3]) : "r"(addr));
}
__device__ __forceinline__ void mma_f16(float* c, const uint32_t* a, uint32_t b0, uint32_t b1) {
    asm volatile(
        "mma.sync.aligned.m16n8k16.row.col.f32.f16.f16.f32 "
        "{%0,%1,%2,%3}, {%4,%5,%6,%7}, {%8,%9}, {%0,%1,%2,%3};"
        : "+f"(c[0]), "+f"(c[1]), "+f"(c[2]), "+f"(c[3])
        : "r"(a[0]), "r"(a[1]), "r"(a[2]), "r"(a[3]), "r"(b0), "r"(b1));
}

// ---------------------------------------------------------------------------
// Pass 0a: q,k -> fp16 hi/mid concatenated arrays + row sum-of-squares
// 160 threads per row, float4 loads (640 = 160*4).
// ---------------------------------------------------------------------------
__global__ __launch_bounds__(160)
void conv_qk_kernel(const float* __restrict__ q, const float* __restrict__ k) {
    int row = blockIdx.x;
    bool isQ = row < BATCH * LQ;
    int r = isQ ? row : row - BATCH * LQ;
    const float4* src = (const float4*)((isQ ? q : k) + (size_t)r * DIM);
    __half* dst = (isQ ? g_qcat : g_kcat) + (size_t)r * 2 * DIM;

    int t = threadIdx.x;
    float4 x4 = src[t];
    float xs[4] = {x4.x, x4.y, x4.z, x4.w};
    float s = 0.f;
    __half2 hi2[2], mid2[2];
#pragma unroll
    for (int u = 0; u < 2; u++) {
        float a = xs[u * 2], bb = xs[u * 2 + 1];
        s = fmaf(a, a, s);
        s = fmaf(bb, bb, s);
        __half ha = __float2half(a), hb = __float2half(bb);
        float fa = __half2float(ha), fb = __half2float(hb);
        float ma = (fa + (a - fa) * 1024.0f) * 0.03125f;
        float mb = (fb + (bb - fb) * 1024.0f) * 0.03125f;
        hi2[u] = __halves2half2(ha, hb);
        mid2[u] = __halves2half2(__float2half(ma), __float2half(mb));
    }
    *(__half2*)(dst + t * 4) = hi2[0];
    *(__half2*)(dst + t * 4 + 2) = hi2[1];
    *(__half2*)(dst + DIM + t * 4) = mid2[0];
    *(__half2*)(dst + DIM + t * 4 + 2) = mid2[1];

#pragma unroll
    for (int off = 16; off > 0; off >>= 1)
        s += __shfl_down_sync(0xffffffffu, s, off);
    __shared__ float ws[5];
    if ((t & 31) == 0) ws[t >> 5] = s;
    __syncthreads();
    if (t == 0) {
        float tt = ws[0] + ws[1] + ws[2] + ws[3] + ws[4];
        if (isQ) g_qq[r] = tt; else g_kk[r] = tt;
    }
}

// ---------------------------------------------------------------------------
// Pass 0b: v -> transposed fp16: g_v16[(b*DIM+d)*LK + k]
// ---------------------------------------------------------------------------
__global__ __launch_bounds__(256)
void conv_v_kernel(const float* __restrict__ v) {
    __shared__ float tile[32][33];
    int b = blockIdx.z;
    int k0 = blockIdx.x * 32;
    int d0 = blockIdx.y * 32;
    int tx = threadIdx.x, ty = threadIdx.y;
#pragma unroll
    for (int i = ty; i < 32; i += 8)
        tile[i][tx] = v[((size_t)b * LK + k0 + i) * DIM + d0 + tx];
    __syncthreads();
#pragma unroll
    for (int i = ty; i < 32; i += 8) {
        float x = tile[tx][i];  // v[k0+tx][d0+i]
        g_v16[((size_t)b * DIM + d0 + i) * LK + k0 + tx] = __float2half(x);
    }
}

// ---------------------------------------------------------------------------
// mma.sync fp16 GEMM. CTA tile MT x NT, warps of 64x64 in (MT/64, NT/64).
// NPASS=2 (merged split: pass0 = hi*hi, then acc *= (1-2^-10), pass1 adds
//          e*mid*mid via pre-scaled operands; rows of 2*KDIM)
// NPASS=1 (plain fp16, rows of KDIM).
// NSTAGE-deep cp.async pipeline, 32-wide k chunks.
// LOGITS: C = (2*acc - qq[m] - kk[n]) / 13.
// ---------------------------------------------------------------------------
template <int MT, int NT, int KDIM, int NPASS, bool LOGITS, int BROWS, int NSTAGE>
__global__ __launch_bounds__((MT / 64) * (NT / 64) * 32, 256 / ((MT / 64) * (NT / 64) * 32))
void gemm_mma_kernel(const uint16_t* __restrict__ Ag,
                     const uint16_t* __restrict__ Bg,
                     float* __restrict__ C, int ldc) {
    constexpr int WM = MT / 64;
    constexpr int WN = NT / 64;
    constexpr int NTHR = WM * WN * 32;
    constexpr int STRIDE = NPASS * KDIM;
    constexpr int KCH = KDIM / 32;      // 32-wide k chunks per pass
    constexpr int NCH = NPASS * KCH;
    constexpr int ABYTES = MT * 64;     // MT rows x 32 elems x 2B
    constexpr int BBYTES = NT * 64;

    extern __shared__ char dsm[];
    const uint32_t uA = smem_u32(dsm);
    const uint32_t uB = uA + NSTAGE * ABYTES;

    int t = threadIdx.x;
    int wid = t >> 5, lane = t & 31;
    int warp_m = wid % WM;
    int warp_n = wid / WM;
    int b = blockIdx.z;
    int m0 = blockIdx.y * MT;
    int n0 = blockIdx.x * NT;
    size_t arow0 = (size_t)b * LQ + m0;
    size_t brow0 = (size_t)b * BROWS + n0;

    auto load_chunk = [&](int ck, int st) {
        int pass = ck / KCH;
        int kc = (ck - pass * KCH) * 32;
        int off = (pass == 1) ? KDIM : 0;
        const uint16_t* ab = Ag + arow0 * STRIDE + off + kc;
        const uint16_t* bb = Bg + brow0 * STRIDE + off + kc;
#pragma unroll
        for (int p = t; p < MT * 4; p += NTHR) {
            int row = p >> 2, c = p & 3;
            int cs = c ^ ((row >> 1) & 3);
            cp16(uA + st * ABYTES + row * 64 + cs * 16, ab + (size_t)row * STRIDE + c * 8);
        }
#pragma unroll
        for (int p = t; p < NT * 4; p += NTHR) {
            int row = p >> 2, c = p & 3;
            int cs = c ^ ((row >> 1) & 3);
            cp16(uB + st * BBYTES + row * 64 + cs * 16, bb + (size_t)row * STRIDE + c * 8);
        }
    };

    float acc[4][8][4];
#pragma unroll
    for (int i = 0; i < 4; i++)
#pragma unroll
        for (int j = 0; j < 8; j++)
#pragma unroll
            for (int u = 0; u < 4; u++) acc[i][j][u] = 0.f;

    // prologue
#pragma unroll
    for (int s = 0; s < NSTAGE - 1; s++) {
        if (s < NCH) load_chunk(s, s);
        asm volatile("cp.async.commit_group;" ::: "memory");
    }

    int lr16 = lane & 15;          // row within 16-row tile
    int hi16 = lane >> 4;          // 16B chunk selector within k16

    for (int s = 0; s < NCH; s++) {
        int pf = s + NSTAGE - 1;
        if (pf < NCH) load_chunk(pf, pf % NSTAGE);
        asm volatile("cp.async.commit_group;" ::: "memory");
        asm volatile("cp.async.wait_group %0;" :: "n"(NSTAGE - 1) : "memory");
        __syncthreads();

        // pass boundary: acc = (1 - e) * pass0 before pass1 MMAs begin
        if (NPASS == 2 && s == KCH) {
#pragma unroll
            for (int i = 0; i < 4; i++)
#pragma unroll
                for (int j = 0; j < 8; j++)
#pragma unroll
                    for (int u = 0; u < 4; u++)
                        acc[i][j][u] *= 0.9990234375f;   // 1 - 2^-10 (exact fp32)
        }

        int st = s % NSTAGE;
        uint32_t aBase = uA + st * ABYTES;
        uint32_t bBase = uB + st * BBYTES;
#pragma unroll
        for (int ks = 0; ks < 2; ks++) {
            int c = ks * 2 + hi16;
            uint32_t afr[4][4];
#pragma unroll
            for (int mt = 0; mt < 4; mt++) {
                int row = warp_m * 64 + mt * 16 + lr16;
                int cs = c ^ ((row >> 1) & 3);
                ldmx4(afr[mt], aBase + row * 64 + cs * 16);
            }
            uint32_t bfr[4][4];
#pragma unroll
            for (int np = 0; np < 4; np++) {
                int row = warp_n * 64 + np * 16 + lr16;
                int cs = c ^ ((row >> 1) & 3);
                ldmx4(bfr[np], bBase + row * 64 + cs * 16);
            }
#pragma unroll
            for (int mt = 0; mt < 4; mt++)
#pragma unroll
                for (int nt = 0; nt < 8; nt++) {
                    int np = nt >> 1, sel = nt & 1;
                    mma_f16(acc[mt][nt], afr[mt], bfr[np][sel], bfr[np][sel + 2]);
                }
        }
        __syncthreads();
    }

    // ---------------- epilogue ----------------
    int lr = lane >> 2;            // 0..7
    int lc = (lane & 3) * 2;       // 0,2,4,6
#pragma unroll
    for (int mt = 0; mt < 4; mt++) {
#pragma unroll
        for (int h = 0; h < 2; h++) {
            int row = m0 + warp_m * 64 + mt * 16 + h * 8 + lr;
            size_t crow = (size_t)b * LQ + row;
            float qqv = LOGITS ? g_qq[crow] : 0.f;
            float* cp = C + crow * ldc + n0 + warp_n * 64 + lc;
#pragma unroll
            for (int nt = 0; nt < 8; nt++) {
                float v0 = acc[mt][nt][h * 2 + 0];
                float v1 = acc[mt][nt][h * 2 + 1];
                if (LOGITS) {
                    int col = b * LK + n0 + warp_n * 64 + nt * 8 + lc;
                    v0 = (2.f * v0 - qqv - g_kk[col]) * INV_TEMP;
                    v1 = (2.f * v1 - qqv - g_kk[col + 1]) * INV_TEMP;
                }
                float2 w; w.x = v0; w.y = v1;
                *(float2*)(cp + nt * 8) = w;
            }
        }
    }
}

// ---------------------------------------------------------------------------
// Pass 3: row softmax (R9 proven layout: strided scalar access, 76% DRAM);
// rewrites log_attn in place, writes attn fp32 and attn fp16 (g_a16).
// ---------------------------------------------------------------------------
__global__ __launch_bounds__(256)
void softmax_kernel(float* __restrict__ logattn, float* __restrict__ attn) {
    size_t row = blockIdx.x;
    float* lp = logattn + row * LK;
    float* ap = attn + row * LK;
    __half* a16 = g_a16 + row * (size_t)LK;
    int t = threadIdx.x;

    float x[8];
#pragma unroll
    for (int j = 0; j < 8; j++) x[j] = lp[t + j * 256];

    float m = x[0];
#pragma unroll
    for (int j = 1; j < 8; j++) m = fmaxf(m, x[j]);
#pragma unroll
    for (int off = 16; off > 0; off >>= 1)
        m = fmaxf(m, __shfl_xor_sync(0xffffffffu, m, off));
    __shared__ float red[8];
    __shared__ float bval;
    if ((t & 31) == 0) red[t >> 5] = m;
    __syncthreads();
    if (t == 0) {
        float mm = red[0];
#pragma unroll
        for (int w = 1; w < 8; w++) mm = fmaxf(mm, red[w]);
        bval = mm;
    }
    __syncthreads();
    m = bval;

    float s = 0.f;
#pragma unroll
    for (int j = 0; j < 8; j++) s += expf(x[j] - m);
#pragma unroll
    for (int off = 16; off > 0; off >>= 1)
        s += __shfl_xor_sync(0xffffffffu, s, off);
    __syncthreads();
    if ((t & 31) == 0) red[t >> 5] = s;
    __syncthreads();
    if (t == 0) {
        float ss = 0.f;
#pragma unroll
        for (int w = 0; w < 8; w++) ss += red[w];
        bval = m + logf(ss);
    }
    __syncthreads();
    float lse = bval;

#pragma unroll
    for (int j = 0; j < 8; j++) {
        int idx = t + j * 256;
        float la = x[j] - lse;
        float a = expf(la);
        lp[idx] = la;
        ap[idx] = a;
        a16[idx] = __float2half(a);
    }
}

// ---------------------------------------------------------------------------
extern "C" void kernel_launch(void* const* d_in, const int* in_sizes, int n_in,
                              void* d_out, int out_size) {
    const float* q = (const float*)d_in[0];
    const float* k = (const float*)d_in[1];
    const float* v = (const float*)d_in[2];

    float* out = (float*)d_out;                            // (B, Lq, D)
    float* attn = out + (size_t)BATCH * LQ * DIM;          // (B, Lq, Lk)
    float* logattn = attn + (size_t)BATCH * LQ * LK;       // (B, Lq, Lk)

    // GEMM1: 128x256, 8 warps, 4 stages, fp16 merged 2-pass: smem = 96KB
    constexpr int SM1 = 4 * (128 * 64 + 256 * 64);
    // GEMM2: 64x128, 2 warps, 4 stages, fp16 1-pass: smem = 48KB
    constexpr int SM2 = 4 * (64 * 64 + 128 * 64);

    auto* k1 = gemm_mma_kernel<128, 256, DIM, 2, true, LK, 4>;
    auto* k2 = gemm_mma_kernel<64, 128, LK, 1, false, DIM, 4>;
    cudaFuncSetAttribute(k1, cudaFuncAttributeMaxDynamicSharedMemorySize, SM1);
    cudaFuncSetAttribute(k2, cudaFuncAttributeMaxDynamicSharedMemorySize, SM2);

    // Side stream + events for conv_v overlap (created once; host-side objects,
    // no device memory). Graph capture records the fork/join dependencies.
    static cudaStream_t s2 = nullptr;
    static cudaEvent_t evFork = nullptr, evJoin = nullptr;
    if (s2 == nullptr) {
        cudaStreamCreateWithFlags(&s2, cudaStreamNonBlocking);
        cudaEventCreateWithFlags(&evFork, cudaEventDisableTiming);
        cudaEventCreateWithFlags(&evJoin, cudaEventDisableTiming);
    }

    // Fork: conv_v runs on s2 concurrently with the conv_qk -> GEMM1 -> softmax
    // chain (conv_v only feeds GEMM2).
    cudaEventRecord(evFork, 0);
    cudaStreamWaitEvent(s2, evFork, 0);
    {
        dim3 g(LK / 32, DIM / 32, BATCH);
        conv_v_kernel<<<g, dim3(32, 8), 0, s2>>>(v);
    }
    cudaEventRecord(evJoin, s2);

    // Main chain
    conv_qk_kernel<<<2 * BATCH * LQ, 160>>>(q, k);

    // Pass 1: logits (into log_attn region): A=qcat [B*LQ,1280], B=kcat [B*LK,1280]
    {
        uint16_t* qc; cudaGetSymbolAddress((void**)&qc, g_qcat);
        uint16_t* kc; cudaGetSymbolAddress((void**)&kc, g_kcat);
        dim3 g(LK / 256, LQ / 128, BATCH);
        k1<<<g, 256, SM1>>>(qc, kc, logattn, LK);
    }

    // Pass 2: softmax (in-place log_attn, attn fp32, attn fp16)
    softmax_kernel<<<BATCH * LQ, 256>>>(logattn, attn);

    // Join: GEMM2 needs g_v16 from conv_v
    cudaStreamWaitEvent(0, evJoin, 0);

    // Pass 3: out = attn @ V: A=g_a16 [B*LQ,2048], B=g_v16 [B*DIM,2048]
    {
        uint16_t* ac; cudaGetSymbolAddress((void**)&ac, g_a16);
        uint16_t* vt; cudaGetSymbolAddress((void**)&vt, g_v16);
        dim3 g(DIM / 128, LQ / 64, BATCH);
        k2<<<g, 64, SM2>>>(ac, vt, out, DIM);
    }
}